// round 15
// baseline (speedup 1.0000x reference)
#include <cuda_runtime.h>
#include <cuda_fp16.h>
#include <cstdint>

#define N_NODES 50000
#define D 128
#define CVT_BLOCKS ((N_NODES * D / 8 + 255) / 256)    // 3125 (2 float4 per thread)
#define PACK_BLOCKS 8                                 // 2048 threads
#define BUCKET 64
#define MAX_OFLOW 800000
#define EPT 4
#define GEMM_ROW_BLOCKS ((N_NODES + 255) / 256)       // 196

// ---------------------------------------------------------------------------
// Device scratch
// ---------------------------------------------------------------------------
__device__ __half g_xh[(size_t)N_NODES * D];      // fp16 mirror of x
__device__ __half g_hf[(size_t)N_NODES * D];      // fp16 aggregated features
__device__ int    g_cnt[N_NODES];
__device__ int    g_bucket[(size_t)N_NODES * BUCKET];
__device__ int    g_oflow_cnt;
__device__ int    g_oflow_src[MAX_OFLOW];
__device__ int    g_oflow_dst[MAX_OFLOW];
// W packed fp16 (single precision term), layout [t(16)][dks(4)][lane(32)] x float4
//   n = t*8 + lane/4 ; k0 = dks*32 + (lane&3)*8
//   {bh(k0,k0+1), bh(k0+2,k0+3), bh(k0+4,k0+5), bh(k0+6,k0+7)}
__device__ float4 g_Wpack[16 * 4 * 32];

// ---------------------------------------------------------------------------
// helpers
// ---------------------------------------------------------------------------
__device__ __forceinline__ void mma_f16(float* acc,
                                        uint32_t a0, uint32_t a1,
                                        uint32_t a2, uint32_t a3,
                                        uint32_t b0, uint32_t b1) {
    asm volatile(
        "mma.sync.aligned.m16n8k16.row.col.f32.f16.f16.f32 "
        "{%0,%1,%2,%3}, {%4,%5,%6,%7}, {%8,%9}, {%0,%1,%2,%3};"
        : "+f"(acc[0]), "+f"(acc[1]), "+f"(acc[2]), "+f"(acc[3])
        : "r"(a0), "r"(a1), "r"(a2), "r"(a3), "r"(b0), "r"(b1));
}

__device__ __forceinline__ uint32_t pack_h2(float lo, float hi) {
    __half2 h = __floats2half2_rn(lo, hi);
    return *reinterpret_cast<uint32_t*>(&h);
}

__device__ __forceinline__ void acc_row_fp16(float4& acc, int s, int lane) {
    uint2 p = __ldg(reinterpret_cast<const uint2*>(g_xh + (size_t)s * D) + lane);
    float2 f0 = __half22float2(*reinterpret_cast<__half2*>(&p.x));
    float2 f1 = __half22float2(*reinterpret_cast<__half2*>(&p.y));
    acc.x += f0.x; acc.y += f0.y; acc.z += f1.x; acc.w += f1.y;
}

// ---------------------------------------------------------------------------
// Kernel 1: init — x->fp16 (2 float4/thread for MLP), zero counters, pack W.
// ---------------------------------------------------------------------------
__global__ void init_kernel(const float* __restrict__ x,
                            const float* __restrict__ W) {
    int bid = blockIdx.x;
    if (bid == 0 && threadIdx.x == 0) g_oflow_cnt = 0;
    if (bid < CVT_BLOCKS) {
        int tix = bid * 256 + threadIdx.x;
        const int n4 = N_NODES * D / 4;
        int i0 = tix * 2;
        if (i0 < n4) {
            float4 v0 = __ldg(reinterpret_cast<const float4*>(x) + i0);
            float4 v1 = __ldg(reinterpret_cast<const float4*>(x) + i0 + 1);
            uint4 packed = make_uint4(pack_h2(v0.x, v0.y), pack_h2(v0.z, v0.w),
                                      pack_h2(v1.x, v1.y), pack_h2(v1.z, v1.w));
            *reinterpret_cast<uint4*>(reinterpret_cast<uint2*>(g_xh) + i0) = packed;
        }
        if (tix < N_NODES / 4) reinterpret_cast<int4*>(g_cnt)[tix] = make_int4(0, 0, 0, 0);
        return;
    }
    int idx = (bid - CVT_BLOCKS) * 256 + threadIdx.x;   // 0..2047
    if (idx >= 16 * 4 * 32) return;
    int lane = idx & 31;
    int dks = (idx >> 5) & 3;
    int t = idx >> 7;
    int n = t * 8 + (lane >> 2);
    int k0 = dks * 32 + (lane & 3) * 8;

    const float* wr = W + n * D + k0;
    float4 w01 = __ldg(reinterpret_cast<const float4*>(wr));
    float4 w23 = __ldg(reinterpret_cast<const float4*>(wr + 4));

    float4 v;
    v.x = __uint_as_float(pack_h2(w01.x, w01.y));
    v.y = __uint_as_float(pack_h2(w01.z, w01.w));
    v.z = __uint_as_float(pack_h2(w23.x, w23.y));
    v.w = __uint_as_float(pack_h2(w23.z, w23.w));
    g_Wpack[idx] = v;
}

// ---------------------------------------------------------------------------
// Kernel 2: place — bucket src ids by dst, EPT edges/thread (atomic MLP).
// ---------------------------------------------------------------------------
__global__ void place_kernel(const int* __restrict__ src,
                             const int* __restrict__ dst,
                             int n_edges) {
    int tix = blockIdx.x * blockDim.x + threadIdx.x;
    int e0 = tix * EPT;
    if (e0 >= n_edges) return;

    if (e0 + EPT <= n_edges) {
        int4 s4 = __ldg(reinterpret_cast<const int4*>(src + e0));
        int4 d4 = __ldg(reinterpret_cast<const int4*>(dst + e0));
        int ss[EPT] = {s4.x, s4.y, s4.z, s4.w};
        int dd[EPT] = {d4.x, d4.y, d4.z, d4.w};
        int pos[EPT];
#pragma unroll
        for (int u = 0; u < EPT; u++) pos[u] = atomicAdd(&g_cnt[dd[u]], 1);
#pragma unroll
        for (int u = 0; u < EPT; u++) {
            if (pos[u] < BUCKET) {
                g_bucket[(size_t)dd[u] * BUCKET + pos[u]] = ss[u];
            } else {
                int o = atomicAdd(&g_oflow_cnt, 1);
                if (o < MAX_OFLOW) { g_oflow_src[o] = ss[u]; g_oflow_dst[o] = dd[u]; }
            }
        }
    } else {
        for (int e = e0; e < n_edges; e++) {
            int s = __ldg(src + e);
            int d = __ldg(dst + e);
            int pos = atomicAdd(&g_cnt[d], 1);
            if (pos < BUCKET) {
                g_bucket[(size_t)d * BUCKET + pos] = s;
            } else {
                int o = atomicAdd(&g_oflow_cnt, 1);
                if (o < MAX_OFLOW) { g_oflow_src[o] = s; g_oflow_dst[o] = d; }
            }
        }
    }
}

// ---------------------------------------------------------------------------
// Kernel 3: gather — one warp per node; overflow handled inline.
// ---------------------------------------------------------------------------
__global__ void gather_kernel() {
    int gw = (blockIdx.x * blockDim.x + threadIdx.x) >> 5;
    int lane = threadIdx.x & 31;
    if (gw >= N_NODES) return;

    int deg = g_cnt[gw];
    int n = min(deg, BUCKET);

    float4 acc = make_float4(0.f, 0.f, 0.f, 0.f);

    if (n > 0) {
        const int* bp = g_bucket + (size_t)gw * BUCKET;
        int s0 = (lane < n) ? __ldg(bp + lane) : 0;
        int s1 = (lane + 32 < n) ? __ldg(bp + lane + 32) : 0;

        int full = min(n, 32);
        int j = 0;
        for (; j + 1 < full; j += 2) {
            int sa = __shfl_sync(0xffffffffu, s0, j);
            int sb = __shfl_sync(0xffffffffu, s0, j + 1);
            uint2 pa = __ldg(reinterpret_cast<const uint2*>(g_xh + (size_t)sa * D) + lane);
            uint2 pb = __ldg(reinterpret_cast<const uint2*>(g_xh + (size_t)sb * D) + lane);
            float2 fa0 = __half22float2(*reinterpret_cast<__half2*>(&pa.x));
            float2 fa1 = __half22float2(*reinterpret_cast<__half2*>(&pa.y));
            float2 fb0 = __half22float2(*reinterpret_cast<__half2*>(&pb.x));
            float2 fb1 = __half22float2(*reinterpret_cast<__half2*>(&pb.y));
            acc.x += fa0.x + fb0.x;
            acc.y += fa0.y + fb0.y;
            acc.z += fa1.x + fb1.x;
            acc.w += fa1.y + fb1.y;
        }
        for (; j < full; j++) {
            int sa = __shfl_sync(0xffffffffu, s0, j);
            acc_row_fp16(acc, sa, lane);
        }
        for (j = 32; j < n; j++) {
            int sa = __shfl_sync(0xffffffffu, s1, j - 32);
            acc_row_fp16(acc, sa, lane);
        }
    }

    if (deg > BUCKET) {   // never taken for this input; correctness guard
        int m = g_oflow_cnt;
        if (m > MAX_OFLOW) m = MAX_OFLOW;
        for (int e = 0; e < m; e++) {
            if (__ldg(&g_oflow_dst[e]) == gw)
                acc_row_fp16(acc, __ldg(&g_oflow_src[e]), lane);
        }
    }

    uint2 packed = make_uint2(pack_h2(acc.x, acc.y), pack_h2(acc.z, acc.w));
    reinterpret_cast<uint2*>(g_hf + (size_t)gw * D)[lane] = packed;
}

// ---------------------------------------------------------------------------
// Kernel 4: out = h @ W^T + b, single-term fp16 mma, M=32 rows per warp.
// Block: 8 warps = 256 rows x 64 cols; blockIdx.y = column half.
// Per warp-tile: 128 mma, 32 LDS.128 (4 mma per LDS), 16 LDG.128.
// Bias preloaded into registers; 16KB smem per half.
// ---------------------------------------------------------------------------
#define SB_ELEMS (8 * 4 * 32)              // 1024 float4 = 16KB per column half

__global__ __launch_bounds__(256, 2) void gemm_mma_kernel(
    const float* __restrict__ bias,
    float* __restrict__ out) {

    extern __shared__ float4 sB[];         // [t(8)][dks(4)][lane(32)]

    const int tid = threadIdx.x;
    const int wid = tid >> 5;
    const int lane = tid & 31;
    const int q = lane & 3;
    const int half = blockIdx.y;

    {
        const float4* wsrc = g_Wpack + half * SB_ELEMS;
#pragma unroll
        for (int i = 0; i < SB_ELEMS / 256; i++)
            sB[i * 256 + tid] = __ldg(wsrc + i * 256 + tid);
    }

    // preload bias for this thread's 16 output columns
    float2 bias_r[8];
#pragma unroll
    for (int t = 0; t < 8; t++)
        bias_r[t] = *reinterpret_cast<const float2*>(bias + half * 64 + t * 8 + q * 2);

    const int r0 = blockIdx.x * 256 + wid * 32;
    const int rowA0 = r0 + (lane >> 2);        // m-tile 0
    const int rowA1 = rowA0 + 8;
    const int rowA2 = rowA0 + 16;              // m-tile 1
    const int rowA3 = rowA0 + 24;
    const int rc0 = rowA0 < N_NODES ? rowA0 : N_NODES - 1;
    const int rc1 = rowA1 < N_NODES ? rowA1 : N_NODES - 1;
    const int rc2 = rowA2 < N_NODES ? rowA2 : N_NODES - 1;
    const int rc3 = rowA3 < N_NODES ? rowA3 : N_NODES - 1;
    const uint4* hp0 = reinterpret_cast<const uint4*>(g_hf + (size_t)rc0 * D) + q;
    const uint4* hp1 = reinterpret_cast<const uint4*>(g_hf + (size_t)rc1 * D) + q;
    const uint4* hp2 = reinterpret_cast<const uint4*>(g_hf + (size_t)rc2 * D) + q;
    const uint4* hp3 = reinterpret_cast<const uint4*>(g_hf + (size_t)rc3 * D) + q;

    float acc0[8][4], acc1[8][4];
#pragma unroll
    for (int t = 0; t < 8; t++)
#pragma unroll
        for (int c = 0; c < 4; c++) { acc0[t][c] = 0.f; acc1[t][c] = 0.f; }

    __syncthreads();

#pragma unroll
    for (int dks = 0; dks < 4; dks++) {
        // k = dks*32 + q*8 + {0..7}: one uint4 per row
        uint4 va = __ldg(hp0 + dks * 4);
        uint4 vb = __ldg(hp1 + dks * 4);
        uint4 vc = __ldg(hp2 + dks * 4);
        uint4 vd = __ldg(hp3 + dks * 4);

        const float4* wp = sB + dks * 32 + lane;
#pragma unroll
        for (int t = 0; t < 8; t++) {
            float4 bf = wp[t * 128];       // [t][dks][lane]
            uint32_t b0 = __float_as_uint(bf.x);
            uint32_t b1 = __float_as_uint(bf.y);
            uint32_t b2 = __float_as_uint(bf.z);
            uint32_t b3 = __float_as_uint(bf.w);
            // j=0: k{0..3}
            mma_f16(acc0[t], va.x, vb.x, va.y, vb.y, b0, b1);
            mma_f16(acc1[t], vc.x, vd.x, vc.y, vd.y, b0, b1);
            // j=1: k{4..7}
            mma_f16(acc0[t], va.z, vb.z, va.w, vb.w, b2, b3);
            mma_f16(acc1[t], vc.z, vd.z, vc.w, vd.w, b2, b3);
        }
    }

    // epilogue
#pragma unroll
    for (int t = 0; t < 8; t++) {
        int col = half * 64 + t * 8 + q * 2;
        float b0 = bias_r[t].x;
        float b1 = bias_r[t].y;
        if (rowA0 < N_NODES) {
            float2 v = make_float2(acc0[t][0] + b0, acc0[t][1] + b1);
            *reinterpret_cast<float2*>(out + (size_t)rowA0 * D + col) = v;
        }
        if (rowA1 < N_NODES) {
            float2 v = make_float2(acc0[t][2] + b0, acc0[t][3] + b1);
            *reinterpret_cast<float2*>(out + (size_t)rowA1 * D + col) = v;
        }
        if (rowA2 < N_NODES) {
            float2 v = make_float2(acc1[t][0] + b0, acc1[t][1] + b1);
            *reinterpret_cast<float2*>(out + (size_t)rowA2 * D + col) = v;
        }
        if (rowA3 < N_NODES) {
            float2 v = make_float2(acc1[t][2] + b0, acc1[t][3] + b1);
            *reinterpret_cast<float2*>(out + (size_t)rowA3 * D + col) = v;
        }
    }
}

// ---------------------------------------------------------------------------
// Launch: inputs in metadata order: x, src, dst, W, b
// ---------------------------------------------------------------------------
extern "C" void kernel_launch(void* const* d_in, const int* in_sizes, int n_in,
                              void* d_out, int out_size) {
    const float* x   = (const float*)d_in[0];
    const int*   src = (const int*)d_in[1];
    const int*   dst = (const int*)d_in[2];
    const float* W   = (const float*)d_in[3];
    const float* b   = (const float*)d_in[4];
    float* out = (float*)d_out;

    const int n_edges = in_sizes[1];

    // 1) init: x->fp16, zero counters, pack W (fp16)
    init_kernel<<<CVT_BLOCKS + PACK_BLOCKS, 256>>>(x, W);

    // 2) place: bucket src ids by dst
    {
        int blocks = (n_edges + 256 * EPT - 1) / (256 * EPT);
        place_kernel<<<blocks, 256>>>(src, dst, n_edges);
    }

    // 3) gather: warp per node
    {
        long long total_threads = (long long)N_NODES * 32;
        int blocks = (int)((total_threads + 255) / 256);
        gather_kernel<<<blocks, 256>>>();
    }

    // 4) single-term fp16 tensor-core GEMM + bias, M=32/warp
    {
        static bool attr_set = false;
        if (!attr_set) {
            cudaFuncSetAttribute(gemm_mma_kernel,
                                 cudaFuncAttributeMaxDynamicSharedMemorySize,
                                 SB_ELEMS * sizeof(float4));
            attr_set = true;
        }
        dim3 grid(GEMM_ROW_BLOCKS, 2);
        gemm_mma_kernel<<<grid, 256, SB_ELEMS * sizeof(float4)>>>(b, out);
    }
}

// round 16
// speedup vs baseline: 1.3193x; 1.3193x over previous
#include <cuda_runtime.h>
#include <cuda_fp16.h>
#include <cstdint>

#define N_NODES 50000
#define D 128
#define CVT_BLOCKS ((N_NODES * D / 4 + 255) / 256)    // 6250
#define PACK_BLOCKS 16                                // 4096 threads
#define BUCKET 64
#define MAX_OFLOW 800000
#define EPT 4
#define GEMM_ROW_BLOCKS ((N_NODES + 255) / 256)       // 196

// ---------------------------------------------------------------------------
// Device scratch
// ---------------------------------------------------------------------------
__device__ __half g_xh[(size_t)N_NODES * D];      // fp16 mirror of x
__device__ __half g_hf[(size_t)N_NODES * D];      // fp16 aggregated features
__device__ int    g_cnt[N_NODES];
__device__ int    g_bucket[(size_t)N_NODES * BUCKET];
__device__ int    g_oflow_cnt;
__device__ int    g_oflow_src[MAX_OFLOW];
__device__ int    g_oflow_dst[MAX_OFLOW];
// W packed fp16 hi/lo, layout [t(16)][dks(4)][j(2)][lane(32)] x float4
//   n = t*8 + lane/4 ; k0 = dks*32 + (lane&3)*8 + j*4
__device__ float4 g_Wpack[16 * 4 * 2 * 32];

// ---------------------------------------------------------------------------
// helpers
// ---------------------------------------------------------------------------
__device__ __forceinline__ void mma_f16(float* acc,
                                        uint32_t a0, uint32_t a1,
                                        uint32_t a2, uint32_t a3,
                                        uint32_t b0, uint32_t b1) {
    asm volatile(
        "mma.sync.aligned.m16n8k16.row.col.f32.f16.f16.f32 "
        "{%0,%1,%2,%3}, {%4,%5,%6,%7}, {%8,%9}, {%0,%1,%2,%3};"
        : "+f"(acc[0]), "+f"(acc[1]), "+f"(acc[2]), "+f"(acc[3])
        : "r"(a0), "r"(a1), "r"(a2), "r"(a3), "r"(b0), "r"(b1));
}

__device__ __forceinline__ uint32_t pack_h2(float lo, float hi) {
    __half2 h = __floats2half2_rn(lo, hi);
    return *reinterpret_cast<uint32_t*>(&h);
}

__device__ __forceinline__ void acc_row_fp16(float4& acc, int s, int lane) {
    uint2 p = __ldg(reinterpret_cast<const uint2*>(g_xh + (size_t)s * D) + lane);
    float2 f0 = __half22float2(*reinterpret_cast<__half2*>(&p.x));
    float2 f1 = __half22float2(*reinterpret_cast<__half2*>(&p.y));
    acc.x += f0.x; acc.y += f0.y; acc.z += f1.x; acc.w += f1.y;
}

// ---------------------------------------------------------------------------
// Kernel 1: init — x->fp16, zero g_cnt + oflow counter, pack W (fp16 hi/lo).
// ---------------------------------------------------------------------------
__global__ void init_kernel(const float* __restrict__ x,
                            const float* __restrict__ W) {
    int bid = blockIdx.x;
    if (bid == 0 && threadIdx.x == 0) g_oflow_cnt = 0;
    if (bid < CVT_BLOCKS) {
        int i = bid * 256 + threadIdx.x;
        const int n4 = N_NODES * D / 4;
        if (i < n4) {
            float4 v = __ldg(reinterpret_cast<const float4*>(x) + i);
            uint2 packed = make_uint2(pack_h2(v.x, v.y), pack_h2(v.z, v.w));
            reinterpret_cast<uint2*>(g_xh)[i] = packed;
        }
        if (i < N_NODES / 4) reinterpret_cast<int4*>(g_cnt)[i] = make_int4(0, 0, 0, 0);
        return;
    }
    int idx = (bid - CVT_BLOCKS) * 256 + threadIdx.x;   // 0..4095
    if (idx >= 16 * 4 * 2 * 32) return;
    int lane = idx & 31;
    int j = (idx >> 5) & 1;
    int dks = (idx >> 6) & 3;
    int t = idx >> 8;
    int n = t * 8 + (lane >> 2);
    int k0 = dks * 32 + (lane & 3) * 8 + j * 4;

    float w0 = __ldg(W + n * D + k0 + 0);
    float w1 = __ldg(W + n * D + k0 + 1);
    float w2 = __ldg(W + n * D + k0 + 2);
    float w3 = __ldg(W + n * D + k0 + 3);

    __half wh0 = __float2half_rn(w0), wh1 = __float2half_rn(w1);
    __half wh2 = __float2half_rn(w2), wh3 = __float2half_rn(w3);
    float r0 = w0 - __half2float(wh0), r1 = w1 - __half2float(wh1);
    float r2 = w2 - __half2float(wh2), r3 = w3 - __half2float(wh3);

    float4 v;
    v.x = __uint_as_float(pack_h2(__half2float(wh0), __half2float(wh1)));
    v.y = __uint_as_float(pack_h2(__half2float(wh2), __half2float(wh3)));
    v.z = __uint_as_float(pack_h2(r0, r1));
    v.w = __uint_as_float(pack_h2(r2, r3));
    g_Wpack[idx] = v;
}

// ---------------------------------------------------------------------------
// Kernel 2: place — bucket src ids by dst, EPT edges/thread (atomic MLP).
// PDL: wait for init (g_cnt zeroing) before any atomics.
// ---------------------------------------------------------------------------
__global__ void place_kernel(const int* __restrict__ src,
                             const int* __restrict__ dst,
                             int n_edges) {
#if __CUDA_ARCH__ >= 900
    cudaGridDependencySynchronize();
#endif
    int tix = blockIdx.x * blockDim.x + threadIdx.x;
    int e0 = tix * EPT;
    if (e0 >= n_edges) return;

    if (e0 + EPT <= n_edges) {
        int4 s4 = __ldg(reinterpret_cast<const int4*>(src + e0));
        int4 d4 = __ldg(reinterpret_cast<const int4*>(dst + e0));
        int ss[EPT] = {s4.x, s4.y, s4.z, s4.w};
        int dd[EPT] = {d4.x, d4.y, d4.z, d4.w};
        int pos[EPT];
#pragma unroll
        for (int u = 0; u < EPT; u++) pos[u] = atomicAdd(&g_cnt[dd[u]], 1);
#pragma unroll
        for (int u = 0; u < EPT; u++) {
            if (pos[u] < BUCKET) {
                g_bucket[(size_t)dd[u] * BUCKET + pos[u]] = ss[u];
            } else {
                int o = atomicAdd(&g_oflow_cnt, 1);
                if (o < MAX_OFLOW) { g_oflow_src[o] = ss[u]; g_oflow_dst[o] = dd[u]; }
            }
        }
    } else {
        for (int e = e0; e < n_edges; e++) {
            int s = __ldg(src + e);
            int d = __ldg(dst + e);
            int pos = atomicAdd(&g_cnt[d], 1);
            if (pos < BUCKET) {
                g_bucket[(size_t)d * BUCKET + pos] = s;
            } else {
                int o = atomicAdd(&g_oflow_cnt, 1);
                if (o < MAX_OFLOW) { g_oflow_src[o] = s; g_oflow_dst[o] = d; }
            }
        }
    }
}

// ---------------------------------------------------------------------------
// Kernel 3: gather — one warp per node; overflow handled inline.
// PDL: wait for place.
// ---------------------------------------------------------------------------
__global__ void gather_kernel() {
#if __CUDA_ARCH__ >= 900
    cudaGridDependencySynchronize();
#endif
    int gw = (blockIdx.x * blockDim.x + threadIdx.x) >> 5;
    int lane = threadIdx.x & 31;
    if (gw >= N_NODES) return;

    int deg = g_cnt[gw];
    int n = min(deg, BUCKET);

    float4 acc = make_float4(0.f, 0.f, 0.f, 0.f);

    if (n > 0) {
        const int* bp = g_bucket + (size_t)gw * BUCKET;
        int s0 = (lane < n) ? __ldg(bp + lane) : 0;
        int s1 = (lane + 32 < n) ? __ldg(bp + lane + 32) : 0;

        int full = min(n, 32);
        int j = 0;
        for (; j + 1 < full; j += 2) {
            int sa = __shfl_sync(0xffffffffu, s0, j);
            int sb = __shfl_sync(0xffffffffu, s0, j + 1);
            uint2 pa = __ldg(reinterpret_cast<const uint2*>(g_xh + (size_t)sa * D) + lane);
            uint2 pb = __ldg(reinterpret_cast<const uint2*>(g_xh + (size_t)sb * D) + lane);
            float2 fa0 = __half22float2(*reinterpret_cast<__half2*>(&pa.x));
            float2 fa1 = __half22float2(*reinterpret_cast<__half2*>(&pa.y));
            float2 fb0 = __half22float2(*reinterpret_cast<__half2*>(&pb.x));
            float2 fb1 = __half22float2(*reinterpret_cast<__half2*>(&pb.y));
            acc.x += fa0.x + fb0.x;
            acc.y += fa0.y + fb0.y;
            acc.z += fa1.x + fb1.x;
            acc.w += fa1.y + fb1.y;
        }
        for (; j < full; j++) {
            int sa = __shfl_sync(0xffffffffu, s0, j);
            acc_row_fp16(acc, sa, lane);
        }
        for (j = 32; j < n; j++) {
            int sa = __shfl_sync(0xffffffffu, s1, j - 32);
            acc_row_fp16(acc, sa, lane);
        }
    }

    if (deg > BUCKET) {   // never taken for this input; correctness guard
        int m = g_oflow_cnt;
        if (m > MAX_OFLOW) m = MAX_OFLOW;
        for (int e = 0; e < m; e++) {
            if (__ldg(&g_oflow_dst[e]) == gw)
                acc_row_fp16(acc, __ldg(&g_oflow_src[e]), lane);
        }
    }

    uint2 packed = make_uint2(pack_h2(acc.x, acc.y), pack_h2(acc.z, acc.w));
    reinterpret_cast<uint2*>(g_hf + (size_t)gw * D)[lane] = packed;
}

// ---------------------------------------------------------------------------
// Kernel 4: out = h @ W^T + b via 2-term fp16 mma, M=32 rows per warp.
// PDL: wait for gather BEFORE touching g_Wpack/g_hf.
// Bias preloaded into registers.
// ---------------------------------------------------------------------------
#define SB_ELEMS (8 * 4 * 2 * 32)          // 2048 float4 = 32KB per column half

__global__ __launch_bounds__(256, 2) void gemm_mma_kernel(
    const float* __restrict__ bias,
    float* __restrict__ out) {

#if __CUDA_ARCH__ >= 900
    cudaGridDependencySynchronize();
#endif

    extern __shared__ float4 sB[];         // [t(8)][dks(4)][j(2)][lane(32)]

    const int tid = threadIdx.x;
    const int wid = tid >> 5;
    const int lane = tid & 31;
    const int q = lane & 3;
    const int half = blockIdx.y;

    {
        const float4* wsrc = g_Wpack + half * SB_ELEMS;
#pragma unroll
        for (int i = 0; i < SB_ELEMS / 256; i++)
            sB[i * 256 + tid] = __ldg(wsrc + i * 256 + tid);
    }

    // preload bias for this thread's 16 output columns
    float2 bias_r[8];
#pragma unroll
    for (int t = 0; t < 8; t++)
        bias_r[t] = *reinterpret_cast<const float2*>(bias + half * 64 + t * 8 + q * 2);

    const int r0 = blockIdx.x * 256 + wid * 32;
    const int rowA0 = r0 + (lane >> 2);        // m-tile 0
    const int rowA1 = rowA0 + 8;
    const int rowA2 = rowA0 + 16;              // m-tile 1
    const int rowA3 = rowA0 + 24;
    const int rc0 = rowA0 < N_NODES ? rowA0 : N_NODES - 1;
    const int rc1 = rowA1 < N_NODES ? rowA1 : N_NODES - 1;
    const int rc2 = rowA2 < N_NODES ? rowA2 : N_NODES - 1;
    const int rc3 = rowA3 < N_NODES ? rowA3 : N_NODES - 1;
    const uint4* hp0 = reinterpret_cast<const uint4*>(g_hf + (size_t)rc0 * D) + q;
    const uint4* hp1 = reinterpret_cast<const uint4*>(g_hf + (size_t)rc1 * D) + q;
    const uint4* hp2 = reinterpret_cast<const uint4*>(g_hf + (size_t)rc2 * D) + q;
    const uint4* hp3 = reinterpret_cast<const uint4*>(g_hf + (size_t)rc3 * D) + q;

    float acc0[8][4], acc1[8][4];
#pragma unroll
    for (int t = 0; t < 8; t++)
#pragma unroll
        for (int c = 0; c < 4; c++) { acc0[t][c] = 0.f; acc1[t][c] = 0.f; }

    __syncthreads();

#pragma unroll
    for (int dks = 0; dks < 4; dks++) {
        uint4 va = __ldg(hp0 + dks * 4);
        uint4 vb = __ldg(hp1 + dks * 4);
        uint4 vc = __ldg(hp2 + dks * 4);
        uint4 vd = __ldg(hp3 + dks * 4);

#pragma unroll
        for (int j = 0; j < 2; j++) {
            uint32_t a0 = j ? va.z : va.x, a2 = j ? va.w : va.y;
            uint32_t a1 = j ? vb.z : vb.x, a3 = j ? vb.w : vb.y;
            uint32_t c0 = j ? vc.z : vc.x, c2 = j ? vc.w : vc.y;
            uint32_t c1 = j ? vd.z : vd.x, c3 = j ? vd.w : vd.y;

            const float4* wp = sB + (dks * 2 + j) * 32 + lane;
#pragma unroll
            for (int t = 0; t < 8; t++) {
                float4 bf = wp[t * 256];
                uint32_t bh0 = __float_as_uint(bf.x);
                uint32_t bh1 = __float_as_uint(bf.y);
                uint32_t bl0 = __float_as_uint(bf.z);
                uint32_t bl1 = __float_as_uint(bf.w);
                mma_f16(acc0[t], a0, a1, a2, a3, bh0, bh1);
                mma_f16(acc0[t], a0, a1, a2, a3, bl0, bl1);
                mma_f16(acc1[t], c0, c1, c2, c3, bh0, bh1);
                mma_f16(acc1[t], c0, c1, c2, c3, bl0, bl1);
            }
        }
    }

    // epilogue
#pragma unroll
    for (int t = 0; t < 8; t++) {
        int col = half * 64 + t * 8 + q * 2;
        float b0 = bias_r[t].x;
        float b1 = bias_r[t].y;
        if (rowA0 < N_NODES) {
            float2 v = make_float2(acc0[t][0] + b0, acc0[t][1] + b1);
            *reinterpret_cast<float2*>(out + (size_t)rowA0 * D + col) = v;
        }
        if (rowA1 < N_NODES) {
            float2 v = make_float2(acc0[t][2] + b0, acc0[t][3] + b1);
            *reinterpret_cast<float2*>(out + (size_t)rowA1 * D + col) = v;
        }
        if (rowA2 < N_NODES) {
            float2 v = make_float2(acc1[t][0] + b0, acc1[t][1] + b1);
            *reinterpret_cast<float2*>(out + (size_t)rowA2 * D + col) = v;
        }
        if (rowA3 < N_NODES) {
            float2 v = make_float2(acc1[t][2] + b0, acc1[t][3] + b1);
            *reinterpret_cast<float2*>(out + (size_t)rowA3 * D + col) = v;
        }
    }
}

// ---------------------------------------------------------------------------
// PDL launch helper: dependent launch overlapping producer drain.
// ---------------------------------------------------------------------------
template <typename... Args>
static void launch_pdl(void (*kern)(Args...), dim3 grid, dim3 block,
                       size_t smem, Args... args) {
    cudaLaunchConfig_t cfg = {};
    cfg.gridDim = grid;
    cfg.blockDim = block;
    cfg.dynamicSmemBytes = smem;
    cudaLaunchAttribute attr[1];
    attr[0].id = cudaLaunchAttributeProgrammaticStreamSerialization;
    attr[0].val.programmaticStreamSerializationAllowed = 1;
    cfg.attrs = attr;
    cfg.numAttrs = 1;
    cudaLaunchKernelEx(&cfg, kern, args...);
}

// ---------------------------------------------------------------------------
// Launch: inputs in metadata order: x, src, dst, W, b
// ---------------------------------------------------------------------------
extern "C" void kernel_launch(void* const* d_in, const int* in_sizes, int n_in,
                              void* d_out, int out_size) {
    const float* x   = (const float*)d_in[0];
    const int*   src = (const int*)d_in[1];
    const int*   dst = (const int*)d_in[2];
    const float* W   = (const float*)d_in[3];
    const float* b   = (const float*)d_in[4];
    float* out = (float*)d_out;

    const int n_edges = in_sizes[1];

    // 1) init: x->fp16, zero counters, pack W (fp16 hi/lo)
    init_kernel<<<CVT_BLOCKS + PACK_BLOCKS, 256>>>(x, W);

    // 2) place (PDL: overlaps init drain; syncs on entry)
    {
        int blocks = (n_edges + 256 * EPT - 1) / (256 * EPT);
        launch_pdl(place_kernel, dim3(blocks), dim3(256), 0, src, dst, n_edges);
    }

    // 3) gather (PDL)
    {
        long long total_threads = (long long)N_NODES * 32;
        int blocks = (int)((total_threads + 255) / 256);
        launch_pdl(gather_kernel, dim3(blocks), dim3(256), 0);
    }

    // 4) 2-term fp16 tensor-core GEMM + bias, M=32/warp (PDL)
    {
        static bool attr_set = false;
        if (!attr_set) {
            cudaFuncSetAttribute(gemm_mma_kernel,
                                 cudaFuncAttributeMaxDynamicSharedMemorySize,
                                 SB_ELEMS * sizeof(float4));
            attr_set = true;
        }
        launch_pdl(gemm_mma_kernel, dim3(GEMM_ROW_BLOCKS, 2), dim3(256),
                   SB_ELEMS * sizeof(float4), b, out);
    }
}